// round 8
// baseline (speedup 1.0000x reference)
#include <cuda_runtime.h>
#include <cuda_bf16.h>
#include <cstdint>

#define BATCH   16384
#define IN_DIM  1024
#define OUT_DIM 4096
#define TOPK    409
#define EPS     1.5e-3f
#define MAXCAND 128

#define BM 128
#define BN 256
#define BK 32
#define STAGES 3
#define NPASS 3
#define NCHUNK (NPASS * IN_DIM / BK)  // 96
#define RSTRIDE 80                    // conflict-free for 8-row ldmatrix
#define A_TILE (BM * RSTRIDE)         // 10240
#define B_TILE (BN * RSTRIDE)         // 20480
#define STAGE_BYTES (A_TILE + B_TILE) // 30720
#define SMEM_TOTAL (STAGES * STAGE_BYTES)

__device__ int g_flag;
__device__ __nv_bfloat16 g_xs[2ull * BATCH * IN_DIM];
__device__ __nv_bfloat16 g_ws[2ull * OUT_DIM * IN_DIM];
__constant__ int c_PA[NPASS] = {0, 0, 1};
__constant__ int c_PB[NPASS] = {0, 1, 0};

__device__ __forceinline__ uint32_t smem_u32(const void* p) {
    uint32_t a;
    asm("{ .reg .u64 t; cvta.to.shared.u64 t, %1; cvt.u32.u64 %0, t; }" : "=r"(a) : "l"(p));
    return a;
}
__device__ __forceinline__ void cp16(uint32_t dst, const void* src) {
    asm volatile("cp.async.cg.shared.global [%0], [%1], 16;" :: "r"(dst), "l"(src));
}
__device__ __forceinline__ void ldsm4(uint32_t& r0, uint32_t& r1, uint32_t& r2,
                                      uint32_t& r3, uint32_t addr) {
    asm volatile("ldmatrix.sync.aligned.m8n8.x4.shared.b16 {%0,%1,%2,%3}, [%4];"
                 : "=r"(r0), "=r"(r1), "=r"(r2), "=r"(r3) : "r"(addr));
}
__device__ __forceinline__ void mma_bf16(float& c0, float& c1, float& c2, float& c3,
                                         uint32_t a0, uint32_t a1, uint32_t a2, uint32_t a3,
                                         uint32_t b0, uint32_t b1) {
    asm volatile(
        "mma.sync.aligned.m16n8k16.row.col.f32.bf16.bf16.f32 "
        "{%0,%1,%2,%3}, {%4,%5,%6,%7}, {%8,%9}, {%0,%1,%2,%3};"
        : "+f"(c0), "+f"(c1), "+f"(c2), "+f"(c3)
        : "r"(a0), "r"(a1), "r"(a2), "r"(a3), "r"(b0), "r"(b1));
}

// ---------------------------------------------------------------------------
__global__ void init_flag_kernel() { g_flag = 1; }

__global__ void scan_neg_kernel(const float4* __restrict__ x, int n4) {
    bool neg = false;
    for (int i = blockIdx.x * blockDim.x + threadIdx.x; i < n4;
         i += gridDim.x * blockDim.x) {
        float4 v = x[i];
        neg = neg || (v.x < 0.f) || (v.y < 0.f) || (v.z < 0.f) || (v.w < 0.f);
    }
    if (__syncthreads_or((int)neg)) {
        if (threadIdx.x == 0) g_flag = 0;
    }
}

// ---------------------------------------------------------------------------
__device__ __forceinline__ void split2(float f, __nv_bfloat16& h, __nv_bfloat16& m) {
    h = __float2bfloat16(f);
    m = __float2bfloat16(f - __bfloat162float(h));
}

__global__ void convert_x_kernel(const float2* __restrict__ x) {
    const bool bip = (g_flag != 0);
    const size_t PL = (size_t)BATCH * IN_DIM;
    __nv_bfloat162* p0 = (__nv_bfloat162*)(g_xs);
    __nv_bfloat162* p1 = (__nv_bfloat162*)(g_xs + PL);
    int n2 = (int)(PL / 2);
    for (int i = blockIdx.x * blockDim.x + threadIdx.x; i < n2;
         i += gridDim.x * blockDim.x) {
        float2 v = x[i];
        if (bip) { v.x = 2.f * v.x - 1.f; v.y = 2.f * v.y - 1.f; }
        __nv_bfloat16 hx, mx, hy, my;
        split2(v.x, hx, mx);
        split2(v.y, hy, my);
        p0[i] = __nv_bfloat162(hx, hy);
        p1[i] = __nv_bfloat162(mx, my);
    }
}

__global__ void convert_w_kernel(const float2* __restrict__ w) {
    const size_t PL = (size_t)OUT_DIM * IN_DIM;
    __nv_bfloat162* p0 = (__nv_bfloat162*)(g_ws);
    __nv_bfloat162* p1 = (__nv_bfloat162*)(g_ws + PL);
    int n2 = (int)(PL / 2);
    for (int i = blockIdx.x * blockDim.x + threadIdx.x; i < n2;
         i += gridDim.x * blockDim.x) {
        float2 v = w[i];
        __nv_bfloat16 hx, mx, hy, my;
        split2(v.x, hx, mx);
        split2(v.y, hy, my);
        p0[i] = __nv_bfloat162(hx, hy);
        p1[i] = __nv_bfloat162(mx, my);
    }
}

// ---------------------------------------------------------------------------
// ldmatrix + mma.sync bf16 GEMM, 3-pass split (K'=3072).
// CTA 128x256, 256 threads (2x4 warps), warp tile 64x64, 3-stage cp.async.
// ---------------------------------------------------------------------------
__device__ __forceinline__ void fill_stage(int chunk, uint32_t sbase, int brow,
                                           int bcol, int tid) {
    const int p  = chunk / (IN_DIM / BK);
    const int kc = (chunk % (IN_DIM / BK)) * BK;
    const int st = chunk % STAGES;
    const __nv_bfloat16* xa = g_xs + (size_t)c_PA[p] * BATCH * IN_DIM;
    const __nv_bfloat16* wb = g_ws + (size_t)c_PB[p] * OUT_DIM * IN_DIM;
    const uint32_t abase = sbase + st * STAGE_BYTES;
    const uint32_t bbase = abase + A_TILE;

    // A: 128 rows x 4 segs = 512 cp16 (idx 0..511)
#pragma unroll
    for (int i = 0; i < 2; i++) {
        int idx = tid + i * 256;
        int row = idx >> 2, seg = idx & 3;
        cp16(abase + row * RSTRIDE + seg * 16,
             xa + (size_t)(brow + row) * IN_DIM + kc + seg * 8);
    }
    // B: 256 rows x 4 segs = 1024 cp16 (idx 0..1023)
#pragma unroll
    for (int i = 0; i < 4; i++) {
        int idx = tid + i * 256;
        int row = idx >> 2, seg = idx & 3;
        cp16(bbase + row * RSTRIDE + seg * 16,
             wb + (size_t)(bcol + row) * IN_DIM + kc + seg * 8);
    }
    asm volatile("cp.async.commit_group;" ::: "memory");
}

__global__ __launch_bounds__(256, 1) void gemm_mma_kernel(float* __restrict__ C) {
    extern __shared__ __align__(128) char smem[];
    const uint32_t sbase = smem_u32(smem);
    const int tid  = threadIdx.x;
    const int wid  = tid >> 5;
    const int lane = tid & 31;
    const int wm   = wid >> 2;          // 0..1
    const int wn   = wid & 3;           // 0..3
    const int brow = blockIdx.y * BM;
    const int bcol = blockIdx.x * BN;

    float acc[4][8][4];                 // [mi][n8][frag]
#pragma unroll
    for (int mi = 0; mi < 4; mi++)
#pragma unroll
        for (int nj = 0; nj < 8; nj++)
#pragma unroll
            for (int r = 0; r < 4; r++) acc[mi][nj][r] = 0.f;

    fill_stage(0, sbase, brow, bcol, tid);
    fill_stage(1, sbase, brow, bcol, tid);

    // ldmatrix lane addressing: row = l&15, 16B-half = l>>4
    const int lrow = lane & 15;
    const int lhalf = (lane >> 4) * 16;

    for (int kt = 0; kt < NCHUNK; ++kt) {
        if (kt + 2 < NCHUNK) asm volatile("cp.async.wait_group 1;" ::: "memory");
        else                 asm volatile("cp.async.wait_group 0;" ::: "memory");
        __syncthreads();

        if (kt + 2 < NCHUNK) fill_stage(kt + 2, sbase, brow, bcol, tid);

        const uint32_t abase = sbase + (kt % STAGES) * STAGE_BYTES;
        const uint32_t bbase = abase + A_TILE;

#pragma unroll
        for (int step = 0; step < 2; ++step) {
            const uint32_t kb = step * 32 + lhalf;
            uint32_t a[4][4], b[4][4];
#pragma unroll
            for (int mi = 0; mi < 4; mi++)
                ldsm4(a[mi][0], a[mi][1], a[mi][2], a[mi][3],
                      abase + (wm * 64 + mi * 16 + lrow) * RSTRIDE + kb);
#pragma unroll
            for (int nj = 0; nj < 4; nj++)
                ldsm4(b[nj][0], b[nj][1], b[nj][2], b[nj][3],
                      bbase + (wn * 64 + nj * 16 + lrow) * RSTRIDE + kb);
#pragma unroll
            for (int mi = 0; mi < 4; mi++) {
#pragma unroll
                for (int nj = 0; nj < 4; nj++) {
                    // n-block 2*nj   : frags {r0, r2};  n-block 2*nj+1 : {r1, r3}
                    mma_bf16(acc[mi][2 * nj][0], acc[mi][2 * nj][1],
                             acc[mi][2 * nj][2], acc[mi][2 * nj][3],
                             a[mi][0], a[mi][1], a[mi][2], a[mi][3],
                             b[nj][0], b[nj][2]);
                    mma_bf16(acc[mi][2 * nj + 1][0], acc[mi][2 * nj + 1][1],
                             acc[mi][2 * nj + 1][2], acc[mi][2 * nj + 1][3],
                             a[mi][0], a[mi][1], a[mi][2], a[mi][3],
                             b[nj][1], b[nj][3]);
                }
            }
        }
        __syncthreads();
    }

    // epilogue
    const int erow = brow + wm * 64 + (lane >> 2);
    const int ecol = bcol + wn * 64 + 2 * (lane & 3);
#pragma unroll
    for (int mi = 0; mi < 4; mi++) {
#pragma unroll
        for (int nj = 0; nj < 8; nj++) {
            float* p0 = C + (size_t)(erow + mi * 16) * OUT_DIM + ecol + nj * 8;
            float* p1 = p0 + 8 * OUT_DIM;
            *(float2*)p0 = make_float2(acc[mi][nj][0], acc[mi][nj][1]);
            *(float2*)p1 = make_float2(acc[mi][nj][2], acc[mi][nj][3]);
        }
    }
}

// ---------------------------------------------------------------------------
// top-K with exact-fp32 boundary fixup + relu + L2 normalize (in place)
// ---------------------------------------------------------------------------
__device__ __forceinline__ unsigned f2k(float f) {
    unsigned u = __float_as_uint(f);
    return (u & 0x80000000u) ? ~u : (u | 0x80000000u);
}
__device__ __forceinline__ float k2f(unsigned k) {
    unsigned u = (k & 0x80000000u) ? (k ^ 0x80000000u) : ~k;
    return __uint_as_float(u);
}

__global__ __launch_bounds__(256) void topk_fix_kernel(
    float* __restrict__ out, const float* __restrict__ x, const float* __restrict__ w)
{
    __shared__ float    vals[OUT_DIM];
    __shared__ float    xrow[IN_DIM];
    __shared__ unsigned char inwin[OUT_DIM];
    __shared__ unsigned hist[256];
    __shared__ int      s_cidx[MAXCAND];
    __shared__ float    s_cex[MAXCAND];
    __shared__ int      s_ncand, s_nhi;
    __shared__ unsigned s_bin, s_rank;
    __shared__ float    s_thrx, s_inv;
    __shared__ float    warp_red[8];

    const int tid  = threadIdx.x;
    const int lane = tid & 31;
    const int wid  = tid >> 5;
    const size_t rowoff = (size_t)blockIdx.x * OUT_DIM;

    const float4* src = (const float4*)(out + rowoff);
    for (int i = tid; i < OUT_DIM / 4; i += 256)
        ((float4*)vals)[i] = src[i];
    {
        const bool bip = (g_flag != 0);
        const float4* xs = (const float4*)(x + (size_t)blockIdx.x * IN_DIM);
        for (int i = tid; i < IN_DIM / 4; i += 256) {
            float4 v = xs[i];
            if (bip) {
                v.x = 2.f * v.x - 1.f; v.y = 2.f * v.y - 1.f;
                v.z = 2.f * v.z - 1.f; v.w = 2.f * v.w - 1.f;
            }
            ((float4*)xrow)[i] = v;
        }
    }
    if (tid == 0) { s_ncand = 0; s_nhi = 0; }
    __syncthreads();

    unsigned prefix = 0u, pmask = 0u, rank = TOPK;
    for (int shift = 24; shift >= 0; shift -= 8) {
        hist[tid] = 0u;
        __syncthreads();
        for (int i = tid; i < OUT_DIM; i += 256) {
            unsigned u = f2k(vals[i]);
            if ((u & pmask) == prefix)
                atomicAdd(&hist[(u >> shift) & 0xFFu], 1u);
        }
        __syncthreads();
        for (int off = 1; off < 256; off <<= 1) {
            unsigned add = (tid + off < 256) ? hist[tid + off] : 0u;
            __syncthreads();
            hist[tid] += add;
            __syncthreads();
        }
        const unsigned cs = hist[tid];
        const unsigned nx = (tid < 255) ? hist[tid + 1] : 0u;
        if (cs >= rank && nx < rank) { s_bin = (unsigned)tid; s_rank = rank - nx; }
        __syncthreads();
        prefix |= s_bin << shift;
        pmask  |= 0xFFu << shift;
        rank    = s_rank;
        __syncthreads();
    }
    const float thr = k2f(prefix);

    int local_hi = 0;
    for (int i = tid; i < OUT_DIM; i += 256) {
        float v = vals[i];
        unsigned char f = 0;
        if (fabsf(v - thr) <= EPS) {
            int p = atomicAdd(&s_ncand, 1);
            if (p < MAXCAND) { s_cidx[p] = i; f = 1; }
            else if (v > thr) local_hi++;
        } else if (v > thr) {
            local_hi++;
        }
        inwin[i] = f;
    }
    atomicAdd(&s_nhi, local_hi);
    __syncthreads();

    const int nc = min(s_ncand, MAXCAND);
    const int kwin = TOPK - s_nhi;

    for (int c = wid; c < nc; c += 8) {
        const float* wr = w + (size_t)s_cidx[c] * IN_DIM;
        float s = 0.f;
        for (int k = lane; k < IN_DIM; k += 32)
            s = fmaf(xrow[k], wr[k], s);
#pragma unroll
        for (int o = 16; o; o >>= 1) s += __shfl_xor_sync(0xFFFFFFFFu, s, o);
        if (lane == 0) { s_cex[c] = s; vals[s_cidx[c]] = s; }
    }
    __syncthreads();

    float tmin = 3.402823466e+38f;
    for (int c = tid; c < nc; c += 256) {
        float e = s_cex[c];
        int gt = 0;
        for (int j = 0; j < nc; j++) gt += (s_cex[j] > e);
        if (gt <= kwin - 1) tmin = fminf(tmin, e);
    }
#pragma unroll
    for (int o = 16; o; o >>= 1) tmin = fminf(tmin, __shfl_xor_sync(0xFFFFFFFFu, tmin, o));
    if (lane == 0) warp_red[wid] = tmin;
    __syncthreads();
    if (tid == 0) {
        float t = warp_red[0];
#pragma unroll
        for (int i = 1; i < 8; i++) t = fminf(t, warp_red[i]);
        s_thrx = t;
    }
    __syncthreads();
    const float thrx = s_thrx;

    float ss = 0.f;
    for (int i = tid; i < OUT_DIM; i += 256) {
        float v = vals[i];
        bool keep = inwin[i] ? (v >= thrx) : (v > thr);
        float e = keep ? fmaxf(v, 0.f) : 0.f;
        ss = fmaf(e, e, ss);
    }
#pragma unroll
    for (int o = 16; o; o >>= 1) ss += __shfl_xor_sync(0xFFFFFFFFu, ss, o);
    if (lane == 0) warp_red[wid] = ss;
    __syncthreads();
    if (tid == 0) {
        float t = 0.f;
#pragma unroll
        for (int i = 0; i < 8; i++) t += warp_red[i];
        s_inv = 1.f / fmaxf(sqrtf(t), 1e-12f);
    }
    __syncthreads();
    const float inv = s_inv;

    float4* dst = (float4*)(out + rowoff);
    for (int g = tid; g < OUT_DIM / 4; g += 256) {
        const int i = g * 4;
        float4 o;
        { float v = vals[i];     o.x = ((inwin[i]     ? (v >= thrx) : (v > thr)) ? fmaxf(v, 0.f) : 0.f) * inv; }
        { float v = vals[i + 1]; o.y = ((inwin[i + 1] ? (v >= thrx) : (v > thr)) ? fmaxf(v, 0.f) : 0.f) * inv; }
        { float v = vals[i + 2]; o.z = ((inwin[i + 2] ? (v >= thrx) : (v > thr)) ? fmaxf(v, 0.f) : 0.f) * inv; }
        { float v = vals[i + 3]; o.w = ((inwin[i + 3] ? (v >= thrx) : (v > thr)) ? fmaxf(v, 0.f) : 0.f) * inv; }
        dst[g] = o;
    }
}

// ---------------------------------------------------------------------------
extern "C" void kernel_launch(void* const* d_in, const int* in_sizes, int n_in,
                              void* d_out, int out_size)
{
    const float* x = (const float*)d_in[0];
    const float* w = (const float*)d_in[1];
    float* out = (float*)d_out;
    (void)in_sizes; (void)n_in; (void)out_size;

    cudaFuncSetAttribute(gemm_mma_kernel,
                         cudaFuncAttributeMaxDynamicSharedMemorySize, SMEM_TOTAL);

    init_flag_kernel<<<1, 1>>>();
    scan_neg_kernel<<<2048, 256>>>((const float4*)x, BATCH * IN_DIM / 4);
    convert_w_kernel<<<4096, 256>>>((const float2*)w);
    convert_x_kernel<<<16384, 256>>>((const float2*)x);

    dim3 ggrid(OUT_DIM / BN, BATCH / BM);     // 16 x 128 CTAs
    gemm_mma_kernel<<<ggrid, 256, SMEM_TOTAL>>>(out);

    topk_fix_kernel<<<BATCH, 256>>>(out, x, w);
}

// round 9
// speedup vs baseline: 1.0505x; 1.0505x over previous
#include <cuda_runtime.h>
#include <cuda_bf16.h>
#include <cstdint>

#define BATCH   16384
#define IN_DIM  1024
#define OUT_DIM 4096
#define TOPK    409
#define EPS     1.5e-3f
#define MAXCAND 128

#define BM 128
#define BN 128
#define BK 32
#define STAGES 3
#define NPASS 3
#define NCHUNK (NPASS * IN_DIM / BK)  // 96
#define RSTRIDE 80                    // conflict-free for 8-row ldmatrix
#define A_TILE (BM * RSTRIDE)         // 10240
#define B_TILE (BN * RSTRIDE)         // 10240
#define STAGE_BYTES (A_TILE + B_TILE) // 20480
#define SMEM_TOTAL (STAGES * STAGE_BYTES)   // 61440 -> 2 CTAs/SM

__device__ int g_flag;
__device__ __nv_bfloat16 g_xs[2ull * BATCH * IN_DIM];
__device__ __nv_bfloat16 g_ws[2ull * OUT_DIM * IN_DIM];
__constant__ int c_PA[NPASS] = {0, 0, 1};
__constant__ int c_PB[NPASS] = {0, 1, 0};

__device__ __forceinline__ uint32_t smem_u32(const void* p) {
    uint32_t a;
    asm("{ .reg .u64 t; cvta.to.shared.u64 t, %1; cvt.u32.u64 %0, t; }" : "=r"(a) : "l"(p));
    return a;
}
__device__ __forceinline__ void cp16(uint32_t dst, const void* src) {
    asm volatile("cp.async.cg.shared.global [%0], [%1], 16;" :: "r"(dst), "l"(src));
}
__device__ __forceinline__ void ldsm4(uint32_t& r0, uint32_t& r1, uint32_t& r2,
                                      uint32_t& r3, uint32_t addr) {
    asm volatile("ldmatrix.sync.aligned.m8n8.x4.shared.b16 {%0,%1,%2,%3}, [%4];"
                 : "=r"(r0), "=r"(r1), "=r"(r2), "=r"(r3) : "r"(addr));
}
__device__ __forceinline__ void mma_bf16(float& c0, float& c1, float& c2, float& c3,
                                         uint32_t a0, uint32_t a1, uint32_t a2, uint32_t a3,
                                         uint32_t b0, uint32_t b1) {
    asm volatile(
        "mma.sync.aligned.m16n8k16.row.col.f32.bf16.bf16.f32 "
        "{%0,%1,%2,%3}, {%4,%5,%6,%7}, {%8,%9}, {%0,%1,%2,%3};"
        : "+f"(c0), "+f"(c1), "+f"(c2), "+f"(c3)
        : "r"(a0), "r"(a1), "r"(a2), "r"(a3), "r"(b0), "r"(b1));
}

// ---------------------------------------------------------------------------
__global__ void init_flag_kernel() { g_flag = 1; }

__global__ void scan_neg_kernel(const float4* __restrict__ x, int n4) {
    bool neg = false;
    for (int i = blockIdx.x * blockDim.x + threadIdx.x; i < n4;
         i += gridDim.x * blockDim.x) {
        float4 v = x[i];
        neg = neg || (v.x < 0.f) || (v.y < 0.f) || (v.z < 0.f) || (v.w < 0.f);
    }
    if (__syncthreads_or((int)neg)) {
        if (threadIdx.x == 0) g_flag = 0;
    }
}

// ---------------------------------------------------------------------------
__device__ __forceinline__ void split2(float f, __nv_bfloat16& h, __nv_bfloat16& m) {
    h = __float2bfloat16(f);
    m = __float2bfloat16(f - __bfloat162float(h));
}

__global__ void convert_x_kernel(const float2* __restrict__ x) {
    const bool bip = (g_flag != 0);
    const size_t PL = (size_t)BATCH * IN_DIM;
    __nv_bfloat162* p0 = (__nv_bfloat162*)(g_xs);
    __nv_bfloat162* p1 = (__nv_bfloat162*)(g_xs + PL);
    int n2 = (int)(PL / 2);
    for (int i = blockIdx.x * blockDim.x + threadIdx.x; i < n2;
         i += gridDim.x * blockDim.x) {
        float2 v = x[i];
        if (bip) { v.x = 2.f * v.x - 1.f; v.y = 2.f * v.y - 1.f; }
        __nv_bfloat16 hx, mx, hy, my;
        split2(v.x, hx, mx);
        split2(v.y, hy, my);
        p0[i] = __nv_bfloat162(hx, hy);
        p1[i] = __nv_bfloat162(mx, my);
    }
}

__global__ void convert_w_kernel(const float2* __restrict__ w) {
    const size_t PL = (size_t)OUT_DIM * IN_DIM;
    __nv_bfloat162* p0 = (__nv_bfloat162*)(g_ws);
    __nv_bfloat162* p1 = (__nv_bfloat162*)(g_ws + PL);
    int n2 = (int)(PL / 2);
    for (int i = blockIdx.x * blockDim.x + threadIdx.x; i < n2;
         i += gridDim.x * blockDim.x) {
        float2 v = w[i];
        __nv_bfloat16 hx, mx, hy, my;
        split2(v.x, hx, mx);
        split2(v.y, hy, my);
        p0[i] = __nv_bfloat162(hx, hy);
        p1[i] = __nv_bfloat162(mx, my);
    }
}

// ---------------------------------------------------------------------------
// ldmatrix + mma.sync bf16 GEMM, 3-pass split (K'=3072).
// CTA 128x128, 256 threads (2x4 warps), warp tile 64x32, 3-stage, occ 2.
// ---------------------------------------------------------------------------
__device__ __forceinline__ void fill_stage(int chunk, uint32_t sbase, int brow,
                                           int bcol, int tid) {
    const int p  = chunk / (IN_DIM / BK);
    const int kc = (chunk % (IN_DIM / BK)) * BK;
    const int st = chunk % STAGES;
    const __nv_bfloat16* xa = g_xs + (size_t)c_PA[p] * BATCH * IN_DIM;
    const __nv_bfloat16* wb = g_ws + (size_t)c_PB[p] * OUT_DIM * IN_DIM;
    const uint32_t abase = sbase + st * STAGE_BYTES;
    const uint32_t bbase = abase + A_TILE;

#pragma unroll
    for (int i = 0; i < 2; i++) {
        int idx = tid + i * 256;           // 0..511
        int row = idx >> 2, seg = idx & 3;
        cp16(abase + row * RSTRIDE + seg * 16,
             xa + (size_t)(brow + row) * IN_DIM + kc + seg * 8);
        cp16(bbase + row * RSTRIDE + seg * 16,
             wb + (size_t)(bcol + row) * IN_DIM + kc + seg * 8);
    }
    asm volatile("cp.async.commit_group;" ::: "memory");
}

__global__ __launch_bounds__(256, 2) void gemm_mma_kernel(float* __restrict__ C) {
    extern __shared__ __align__(128) char smem[];
    const uint32_t sbase = smem_u32(smem);
    const int tid  = threadIdx.x;
    const int wid  = tid >> 5;
    const int lane = tid & 31;
    const int wm   = wid >> 2;          // 0..1
    const int wn   = wid & 3;           // 0..3
    const int brow = blockIdx.y * BM;
    const int bcol = blockIdx.x * BN;

    float acc[4][4][4];                 // [mi][n8][frag]
#pragma unroll
    for (int mi = 0; mi < 4; mi++)
#pragma unroll
        for (int nj = 0; nj < 4; nj++)
#pragma unroll
            for (int r = 0; r < 4; r++) acc[mi][nj][r] = 0.f;

    fill_stage(0, sbase, brow, bcol, tid);
    fill_stage(1, sbase, brow, bcol, tid);

    const int lrow  = lane & 15;
    const int lhalf = (lane >> 4) * 16;

    for (int kt = 0; kt < NCHUNK; ++kt) {
        if (kt + 2 < NCHUNK) asm volatile("cp.async.wait_group 1;" ::: "memory");
        else                 asm volatile("cp.async.wait_group 0;" ::: "memory");
        __syncthreads();

        if (kt + 2 < NCHUNK) fill_stage(kt + 2, sbase, brow, bcol, tid);

        const uint32_t abase = sbase + (kt % STAGES) * STAGE_BYTES;
        const uint32_t bbase = abase + A_TILE;

#pragma unroll
        for (int step = 0; step < 2; ++step) {
            const uint32_t kb = step * 32 + lhalf;
            uint32_t a[4][4], b[2][4];
#pragma unroll
            for (int mi = 0; mi < 4; mi++)
                ldsm4(a[mi][0], a[mi][1], a[mi][2], a[mi][3],
                      abase + (wm * 64 + mi * 16 + lrow) * RSTRIDE + kb);
#pragma unroll
            for (int nj = 0; nj < 2; nj++)
                ldsm4(b[nj][0], b[nj][1], b[nj][2], b[nj][3],
                      bbase + (wn * 32 + nj * 16 + lrow) * RSTRIDE + kb);
#pragma unroll
            for (int mi = 0; mi < 4; mi++) {
#pragma unroll
                for (int nj = 0; nj < 2; nj++) {
                    mma_bf16(acc[mi][2 * nj][0], acc[mi][2 * nj][1],
                             acc[mi][2 * nj][2], acc[mi][2 * nj][3],
                             a[mi][0], a[mi][1], a[mi][2], a[mi][3],
                             b[nj][0], b[nj][2]);
                    mma_bf16(acc[mi][2 * nj + 1][0], acc[mi][2 * nj + 1][1],
                             acc[mi][2 * nj + 1][2], acc[mi][2 * nj + 1][3],
                             a[mi][0], a[mi][1], a[mi][2], a[mi][3],
                             b[nj][1], b[nj][3]);
                }
            }
        }
        __syncthreads();
    }

    // epilogue
    const int erow = brow + wm * 64 + (lane >> 2);
    const int ecol = bcol + wn * 32 + 2 * (lane & 3);
#pragma unroll
    for (int mi = 0; mi < 4; mi++) {
#pragma unroll
        for (int nj = 0; nj < 4; nj++) {
            float* p0 = C + (size_t)(erow + mi * 16) * OUT_DIM + ecol + nj * 8;
            float* p1 = p0 + 8 * OUT_DIM;
            *(float2*)p0 = make_float2(acc[mi][nj][0], acc[mi][nj][1]);
            *(float2*)p1 = make_float2(acc[mi][nj][2], acc[mi][nj][3]);
        }
    }
}

// ---------------------------------------------------------------------------
// top-K with exact-fp32 boundary fixup + relu + L2 normalize (in place)
// ---------------------------------------------------------------------------
__device__ __forceinline__ unsigned f2k(float f) {
    unsigned u = __float_as_uint(f);
    return (u & 0x80000000u) ? ~u : (u | 0x80000000u);
}
__device__ __forceinline__ float k2f(unsigned k) {
    unsigned u = (k & 0x80000000u) ? (k ^ 0x80000000u) : ~k;
    return __uint_as_float(u);
}

__global__ __launch_bounds__(256) void topk_fix_kernel(
    float* __restrict__ out, const float* __restrict__ x, const float* __restrict__ w)
{
    __shared__ float    vals[OUT_DIM];
    __shared__ float    xrow[IN_DIM];
    __shared__ unsigned char inwin[OUT_DIM];
    __shared__ unsigned hist[256];
    __shared__ int      s_cidx[MAXCAND];
    __shared__ float    s_cex[MAXCAND];
    __shared__ int      s_ncand, s_nhi;
    __shared__ unsigned s_bin, s_rank;
    __shared__ float    s_thrx, s_inv;
    __shared__ float    warp_red[8];

    const int tid  = threadIdx.x;
    const int lane = tid & 31;
    const int wid  = tid >> 5;
    const size_t rowoff = (size_t)blockIdx.x * OUT_DIM;

    const float4* src = (const float4*)(out + rowoff);
    for (int i = tid; i < OUT_DIM / 4; i += 256)
        ((float4*)vals)[i] = src[i];
    {
        const bool bip = (g_flag != 0);
        const float4* xs = (const float4*)(x + (size_t)blockIdx.x * IN_DIM);
        for (int i = tid; i < IN_DIM / 4; i += 256) {
            float4 v = xs[i];
            if (bip) {
                v.x = 2.f * v.x - 1.f; v.y = 2.f * v.y - 1.f;
                v.z = 2.f * v.z - 1.f; v.w = 2.f * v.w - 1.f;
            }
            ((float4*)xrow)[i] = v;
        }
    }
    if (tid == 0) { s_ncand = 0; s_nhi = 0; }
    __syncthreads();

    unsigned prefix = 0u, pmask = 0u, rank = TOPK;
    for (int shift = 24; shift >= 0; shift -= 8) {
        hist[tid] = 0u;
        __syncthreads();
        for (int i = tid; i < OUT_DIM; i += 256) {
            unsigned u = f2k(vals[i]);
            if ((u & pmask) == prefix)
                atomicAdd(&hist[(u >> shift) & 0xFFu], 1u);
        }
        __syncthreads();
        for (int off = 1; off < 256; off <<= 1) {
            unsigned add = (tid + off < 256) ? hist[tid + off] : 0u;
            __syncthreads();
            hist[tid] += add;
            __syncthreads();
        }
        const unsigned cs = hist[tid];
        const unsigned nx = (tid < 255) ? hist[tid + 1] : 0u;
        if (cs >= rank && nx < rank) { s_bin = (unsigned)tid; s_rank = rank - nx; }
        __syncthreads();
        prefix |= s_bin << shift;
        pmask  |= 0xFFu << shift;
        rank    = s_rank;
        __syncthreads();
    }
    const float thr = k2f(prefix);

    int local_hi = 0;
    for (int i = tid; i < OUT_DIM; i += 256) {
        float v = vals[i];
        unsigned char f = 0;
        if (fabsf(v - thr) <= EPS) {
            int p = atomicAdd(&s_ncand, 1);
            if (p < MAXCAND) { s_cidx[p] = i; f = 1; }
            else if (v > thr) local_hi++;
        } else if (v > thr) {
            local_hi++;
        }
        inwin[i] = f;
    }
    atomicAdd(&s_nhi, local_hi);
    __syncthreads();

    const int nc = min(s_ncand, MAXCAND);
    const int kwin = TOPK - s_nhi;

    for (int c = wid; c < nc; c += 8) {
        const float* wr = w + (size_t)s_cidx[c] * IN_DIM;
        float s = 0.f;
        for (int k = lane; k < IN_DIM; k += 32)
            s = fmaf(xrow[k], wr[k], s);
#pragma unroll
        for (int o = 16; o; o >>= 1) s += __shfl_xor_sync(0xFFFFFFFFu, s, o);
        if (lane == 0) { s_cex[c] = s; vals[s_cidx[c]] = s; }
    }
    __syncthreads();

    float tmin = 3.402823466e+38f;
    for (int c = tid; c < nc; c += 256) {
        float e = s_cex[c];
        int gt = 0;
        for (int j = 0; j < nc; j++) gt += (s_cex[j] > e);
        if (gt <= kwin - 1) tmin = fminf(tmin, e);
    }
#pragma unroll
    for (int o = 16; o; o >>= 1) tmin = fminf(tmin, __shfl_xor_sync(0xFFFFFFFFu, tmin, o));
    if (lane == 0) warp_red[wid] = tmin;
    __syncthreads();
    if (tid == 0) {
        float t = warp_red[0];
#pragma unroll
        for (int i = 1; i < 8; i++) t = fminf(t, warp_red[i]);
        s_thrx = t;
    }
    __syncthreads();
    const float thrx = s_thrx;

    float ss = 0.f;
    for (int i = tid; i < OUT_DIM; i += 256) {
        float v = vals[i];
        bool keep = inwin[i] ? (v >= thrx) : (v > thr);
        float e = keep ? fmaxf(v, 0.f) : 0.f;
        ss = fmaf(e, e, ss);
    }
#pragma unroll
    for (int o = 16; o; o >>= 1) ss += __shfl_xor_sync(0xFFFFFFFFu, ss, o);
    if (lane == 0) warp_red[wid] = ss;
    __syncthreads();
    if (tid == 0) {
        float t = 0.f;
#pragma unroll
        for (int i = 0; i < 8; i++) t += warp_red[i];
        s_inv = 1.f / fmaxf(sqrtf(t), 1e-12f);
    }
    __syncthreads();
    const float inv = s_inv;

    float4* dst = (float4*)(out + rowoff);
    for (int g = tid; g < OUT_DIM / 4; g += 256) {
        const int i = g * 4;
        float4 o;
        { float v = vals[i];     o.x = ((inwin[i]     ? (v >= thrx) : (v > thr)) ? fmaxf(v, 0.f) : 0.f) * inv; }
        { float v = vals[i + 1]; o.y = ((inwin[i + 1] ? (v >= thrx) : (v > thr)) ? fmaxf(v, 0.f) : 0.f) * inv; }
        { float v = vals[i + 2]; o.z = ((inwin[i + 2] ? (v >= thrx) : (v > thr)) ? fmaxf(v, 0.f) : 0.f) * inv; }
        { float v = vals[i + 3]; o.w = ((inwin[i + 3] ? (v >= thrx) : (v > thr)) ? fmaxf(v, 0.f) : 0.f) * inv; }
        dst[g] = o;
    }
}

// ---------------------------------------------------------------------------
extern "C" void kernel_launch(void* const* d_in, const int* in_sizes, int n_in,
                              void* d_out, int out_size)
{
    const float* x = (const float*)d_in[0];
    const float* w = (const float*)d_in[1];
    float* out = (float*)d_out;
    (void)in_sizes; (void)n_in; (void)out_size;

    cudaFuncSetAttribute(gemm_mma_kernel,
                         cudaFuncAttributeMaxDynamicSharedMemorySize, SMEM_TOTAL);

    init_flag_kernel<<<1, 1>>>();
    scan_neg_kernel<<<2048, 256>>>((const float4*)x, BATCH * IN_DIM / 4);
    convert_w_kernel<<<4096, 256>>>((const float2*)w);
    convert_x_kernel<<<16384, 256>>>((const float2*)x);

    dim3 ggrid(OUT_DIM / BN, BATCH / BM);     // 32 x 128 CTAs
    gemm_mma_kernel<<<ggrid, 256, SMEM_TOTAL>>>(out);

    topk_fix_kernel<<<BATCH, 256>>>(out, x, w);
}

// round 10
// speedup vs baseline: 1.0653x; 1.0140x over previous
#include <cuda_runtime.h>
#include <cuda_fp16.h>
#include <cstdint>

#define BATCH   16384
#define IN_DIM  1024
#define OUT_DIM 4096
#define TOPK    409
#define EPS     1.5e-3f
#define MAXCAND 128

#define BM 128
#define BN 128
#define BK 32
#define STAGES 5
#define NPASS 3
#define NCHUNK (NPASS * IN_DIM / BK)  // 96
#define RSTRIDE 80                    // conflict-free for 8-row ldmatrix
#define A_TILE (BM * RSTRIDE)         // 10240
#define B_TILE (BN * RSTRIDE)         // 10240
#define STAGE_BYTES (A_TILE + B_TILE) // 20480
#define SMEM_TOTAL (STAGES * STAGE_BYTES)   // 102400 -> 2 CTAs/SM (204.8KB/227KB)

__device__ int g_flag;
__device__ __half g_xs[2ull * BATCH * IN_DIM];
__device__ __half g_ws[2ull * OUT_DIM * IN_DIM];
__constant__ int c_PA[NPASS] = {0, 0, 1};
__constant__ int c_PB[NPASS] = {0, 1, 0};

__device__ __forceinline__ uint32_t smem_u32(const void* p) {
    uint32_t a;
    asm("{ .reg .u64 t; cvta.to.shared.u64 t, %1; cvt.u32.u64 %0, t; }" : "=r"(a) : "l"(p));
    return a;
}
__device__ __forceinline__ void cp16(uint32_t dst, const void* src) {
    asm volatile("cp.async.cg.shared.global [%0], [%1], 16;" :: "r"(dst), "l"(src));
}
__device__ __forceinline__ void ldsm4(uint32_t& r0, uint32_t& r1, uint32_t& r2,
                                      uint32_t& r3, uint32_t addr) {
    asm volatile("ldmatrix.sync.aligned.m8n8.x4.shared.b16 {%0,%1,%2,%3}, [%4];"
                 : "=r"(r0), "=r"(r1), "=r"(r2), "=r"(r3) : "r"(addr));
}
__device__ __forceinline__ void mma_f16(float& c0, float& c1, float& c2, float& c3,
                                        uint32_t a0, uint32_t a1, uint32_t a2, uint32_t a3,
                                        uint32_t b0, uint32_t b1) {
    asm volatile(
        "mma.sync.aligned.m16n8k16.row.col.f32.f16.f16.f32 "
        "{%0,%1,%2,%3}, {%4,%5,%6,%7}, {%8,%9}, {%0,%1,%2,%3};"
        : "+f"(c0), "+f"(c1), "+f"(c2), "+f"(c3)
        : "r"(a0), "r"(a1), "r"(a2), "r"(a3), "r"(b0), "r"(b1));
}

// ---------------------------------------------------------------------------
__global__ void init_flag_kernel() { g_flag = 1; }

__global__ void scan_neg_kernel(const float4* __restrict__ x, int n4) {
    bool neg = false;
    for (int i = blockIdx.x * blockDim.x + threadIdx.x; i < n4;
         i += gridDim.x * blockDim.x) {
        float4 v = x[i];
        neg = neg || (v.x < 0.f) || (v.y < 0.f) || (v.z < 0.f) || (v.w < 0.f);
    }
    if (__syncthreads_or((int)neg)) {
        if (threadIdx.x == 0) g_flag = 0;
    }
}

// ---------------------------------------------------------------------------
__device__ __forceinline__ void split2(float f, __half& h, __half& m) {
    h = __float2half_rn(f);
    m = __float2half_rn(f - __half2float(h));
}

__global__ void convert_x_kernel(const float2* __restrict__ x) {
    const bool bip = (g_flag != 0);
    const size_t PL = (size_t)BATCH * IN_DIM;
    __half2* p0 = (__half2*)(g_xs);
    __half2* p1 = (__half2*)(g_xs + PL);
    int n2 = (int)(PL / 2);
    for (int i = blockIdx.x * blockDim.x + threadIdx.x; i < n2;
         i += gridDim.x * blockDim.x) {
        float2 v = x[i];
        if (bip) { v.x = 2.f * v.x - 1.f; v.y = 2.f * v.y - 1.f; }
        __half hx, mx, hy, my;
        split2(v.x, hx, mx);
        split2(v.y, hy, my);
        p0[i] = __halves2half2(hx, hy);
        p1[i] = __halves2half2(mx, my);
    }
}

__global__ void convert_w_kernel(const float2* __restrict__ w) {
    const size_t PL = (size_t)OUT_DIM * IN_DIM;
    __half2* p0 = (__half2*)(g_ws);
    __half2* p1 = (__half2*)(g_ws + PL);
    int n2 = (int)(PL / 2);
    for (int i = blockIdx.x * blockDim.x + threadIdx.x; i < n2;
         i += gridDim.x * blockDim.x) {
        float2 v = w[i];
        __half hx, mx, hy, my;
        split2(v.x, hx, mx);
        split2(v.y, hy, my);
        p0[i] = __halves2half2(hx, hy);
        p1[i] = __halves2half2(mx, my);
    }
}

// ---------------------------------------------------------------------------
// ldmatrix + mma.sync fp16 GEMM, 3-pass split (K'=3072).
// CTA 128x128, 256 threads (2x4 warps), warp tile 64x32, 5-stage, occ 2,
// single __syncthreads per chunk.
// ---------------------------------------------------------------------------
__device__ __forceinline__ void fill_stage(int chunk, uint32_t sbase, int brow,
                                           int bcol, int tid) {
    const int p  = chunk / (IN_DIM / BK);
    const int kc = (chunk % (IN_DIM / BK)) * BK;
    const int st = chunk % STAGES;
    const __half* xa = g_xs + (size_t)c_PA[p] * BATCH * IN_DIM;
    const __half* wb = g_ws + (size_t)c_PB[p] * OUT_DIM * IN_DIM;
    const uint32_t abase = sbase + st * STAGE_BYTES;
    const uint32_t bbase = abase + A_TILE;

#pragma unroll
    for (int i = 0; i < 2; i++) {
        int idx = tid + i * 256;           // 0..511
        int row = idx >> 2, seg = idx & 3;
        cp16(abase + row * RSTRIDE + seg * 16,
             xa + (size_t)(brow + row) * IN_DIM + kc + seg * 8);
        cp16(bbase + row * RSTRIDE + seg * 16,
             wb + (size_t)(bcol + row) * IN_DIM + kc + seg * 8);
    }
    asm volatile("cp.async.commit_group;" ::: "memory");
}

__global__ __launch_bounds__(256, 2) void gemm_mma_kernel(float* __restrict__ C) {
    extern __shared__ __align__(128) char smem[];
    const uint32_t sbase = smem_u32(smem);
    const int tid  = threadIdx.x;
    const int wid  = tid >> 5;
    const int lane = tid & 31;
    const int wm   = wid >> 2;          // 0..1
    const int wn   = wid & 3;           // 0..3
    const int brow = blockIdx.y * BM;
    const int bcol = blockIdx.x * BN;

    float acc[4][4][4];
#pragma unroll
    for (int mi = 0; mi < 4; mi++)
#pragma unroll
        for (int nj = 0; nj < 4; nj++)
#pragma unroll
            for (int r = 0; r < 4; r++) acc[mi][nj][r] = 0.f;

    // prologue: fill STAGES-1 = 4 stages
    fill_stage(0, sbase, brow, bcol, tid);
    fill_stage(1, sbase, brow, bcol, tid);
    fill_stage(2, sbase, brow, bcol, tid);
    fill_stage(3, sbase, brow, bcol, tid);

    const int lrow  = lane & 15;
    const int lhalf = (lane >> 4) * 16;

    for (int kt = 0; kt < NCHUNK; ++kt) {
        if (kt + 4 < NCHUNK) asm volatile("cp.async.wait_group 3;" ::: "memory");
        else                 asm volatile("cp.async.wait_group 0;" ::: "memory");
        __syncthreads();
        // Single barrier per chunk: this barrier also orders iteration kt-1's
        // reads of stage (kt-1)%5 before the fill below overwrites it.
        if (kt + 4 < NCHUNK) fill_stage(kt + 4, sbase, brow, bcol, tid);

        const uint32_t abase = sbase + (kt % STAGES) * STAGE_BYTES;
        const uint32_t bbase = abase + A_TILE;

#pragma unroll
        for (int step = 0; step < 2; ++step) {
            const uint32_t kb = step * 32 + lhalf;
            uint32_t a[4][4], b[2][4];
#pragma unroll
            for (int mi = 0; mi < 4; mi++)
                ldsm4(a[mi][0], a[mi][1], a[mi][2], a[mi][3],
                      abase + (wm * 64 + mi * 16 + lrow) * RSTRIDE + kb);
#pragma unroll
            for (int nj = 0; nj < 2; nj++)
                ldsm4(b[nj][0], b[nj][1], b[nj][2], b[nj][3],
                      bbase + (wn * 32 + nj * 16 + lrow) * RSTRIDE + kb);
#pragma unroll
            for (int mi = 0; mi < 4; mi++) {
#pragma unroll
                for (int nj = 0; nj < 2; nj++) {
                    mma_f16(acc[mi][2 * nj][0], acc[mi][2 * nj][1],
                            acc[mi][2 * nj][2], acc[mi][2 * nj][3],
                            a[mi][0], a[mi][1], a[mi][2], a[mi][3],
                            b[nj][0], b[nj][2]);
                    mma_f16(acc[mi][2 * nj + 1][0], acc[mi][2 * nj + 1][1],
                            acc[mi][2 * nj + 1][2], acc[mi][2 * nj + 1][3],
                            a[mi][0], a[mi][1], a[mi][2], a[mi][3],
                            b[nj][1], b[nj][3]);
                }
            }
        }
    }

    // epilogue
    const int erow = brow + wm * 64 + (lane >> 2);
    const int ecol = bcol + wn * 32 + 2 * (lane & 3);
#pragma unroll
    for (int mi = 0; mi < 4; mi++) {
#pragma unroll
        for (int nj = 0; nj < 4; nj++) {
            float* p0 = C + (size_t)(erow + mi * 16) * OUT_DIM + ecol + nj * 8;
            float* p1 = p0 + 8 * OUT_DIM;
            *(float2*)p0 = make_float2(acc[mi][nj][0], acc[mi][nj][1]);
            *(float2*)p1 = make_float2(acc[mi][nj][2], acc[mi][nj][3]);
        }
    }
}

// ---------------------------------------------------------------------------
// top-K: 24-bit radix threshold + exact-fp32 boundary fixup + relu + L2 norm
// ---------------------------------------------------------------------------
__device__ __forceinline__ unsigned f2k(float f) {
    unsigned u = __float_as_uint(f);
    return (u & 0x80000000u) ? ~u : (u | 0x80000000u);
}
__device__ __forceinline__ float k2f(unsigned k) {
    unsigned u = (k & 0x80000000u) ? (k ^ 0x80000000u) : ~k;
    return __uint_as_float(u);
}

__global__ __launch_bounds__(256) void topk_fix_kernel(
    float* __restrict__ out, const float* __restrict__ x, const float* __restrict__ w)
{
    __shared__ float    vals[OUT_DIM];
    __shared__ float    xrow[IN_DIM];
    __shared__ unsigned char inwin[OUT_DIM];
    __shared__ unsigned hist[256];
    __shared__ int      s_cidx[MAXCAND];
    __shared__ float    s_cex[MAXCAND];
    __shared__ int      s_ncand, s_nhi;
    __shared__ unsigned s_bin, s_rank;
    __shared__ float    s_thrx, s_inv;
    __shared__ float    warp_red[8];

    const int tid  = threadIdx.x;
    const int lane = tid & 31;
    const int wid  = tid >> 5;
    const size_t rowoff = (size_t)blockIdx.x * OUT_DIM;

    const float4* src = (const float4*)(out + rowoff);
    for (int i = tid; i < OUT_DIM / 4; i += 256)
        ((float4*)vals)[i] = src[i];
    {
        const bool bip = (g_flag != 0);
        const float4* xs = (const float4*)(x + (size_t)blockIdx.x * IN_DIM);
        for (int i = tid; i < IN_DIM / 4; i += 256) {
            float4 v = xs[i];
            if (bip) {
                v.x = 2.f * v.x - 1.f; v.y = 2.f * v.y - 1.f;
                v.z = 2.f * v.z - 1.f; v.w = 2.f * v.w - 1.f;
            }
            ((float4*)xrow)[i] = v;
        }
    }
    if (tid == 0) { s_ncand = 0; s_nhi = 0; }
    __syncthreads();

    // 3 radix rounds -> 24-bit prefix; bin width (~6e-5 rel) << EPS, and the
    // exact-fixup below makes the final decisions, so round 4 is unnecessary.
    unsigned prefix = 0u, pmask = 0u, rank = TOPK;
    for (int shift = 24; shift >= 8; shift -= 8) {
        hist[tid] = 0u;
        __syncthreads();
        for (int i = tid; i < OUT_DIM; i += 256) {
            unsigned u = f2k(vals[i]);
            if ((u & pmask) == prefix)
                atomicAdd(&hist[(u >> shift) & 0xFFu], 1u);
        }
        __syncthreads();
        for (int off = 1; off < 256; off <<= 1) {
            unsigned add = (tid + off < 256) ? hist[tid + off] : 0u;
            __syncthreads();
            hist[tid] += add;
            __syncthreads();
        }
        const unsigned cs = hist[tid];
        const unsigned nx = (tid < 255) ? hist[tid + 1] : 0u;
        if (cs >= rank && nx < rank) { s_bin = (unsigned)tid; s_rank = rank - nx; }
        __syncthreads();
        prefix |= s_bin << shift;
        pmask  |= 0xFFu << shift;
        rank    = s_rank;
        __syncthreads();
    }
    const float thr = k2f(prefix);   // low byte 0 => bin lower bound; true Kth in [thr, thr+binw)

    int local_hi = 0;
    for (int i = tid; i < OUT_DIM; i += 256) {
        float v = vals[i];
        unsigned char f = 0;
        if (fabsf(v - thr) <= EPS) {
            int p = atomicAdd(&s_ncand, 1);
            if (p < MAXCAND) { s_cidx[p] = i; f = 1; }
            else if (v > thr) local_hi++;
        } else if (v > thr) {
            local_hi++;
        }
        inwin[i] = f;
    }
    atomicAdd(&s_nhi, local_hi);
    __syncthreads();

    const int nc = min(s_ncand, MAXCAND);
    const int kwin = TOPK - s_nhi;

    for (int c = wid; c < nc; c += 8) {
        const float* wr = w + (size_t)s_cidx[c] * IN_DIM;
        float s = 0.f;
        for (int k = lane; k < IN_DIM; k += 32)
            s = fmaf(xrow[k], wr[k], s);
#pragma unroll
        for (int o = 16; o; o >>= 1) s += __shfl_xor_sync(0xFFFFFFFFu, s, o);
        if (lane == 0) { s_cex[c] = s; vals[s_cidx[c]] = s; }
    }
    __syncthreads();

    float tmin = 3.402823466e+38f;
    for (int c = tid; c < nc; c += 256) {
        float e = s_cex[c];
        int gt = 0;
        for (int j = 0; j < nc; j++) gt += (s_cex[j] > e);
        if (gt <= kwin - 1) tmin = fminf(tmin, e);
    }
#pragma unroll
    for (int o = 16; o; o >>= 1) tmin = fminf(tmin, __shfl_xor_sync(0xFFFFFFFFu, tmin, o));
    if (lane == 0) warp_red[wid] = tmin;
    __syncthreads();
    if (tid == 0) {
        float t = warp_red[0];
#pragma unroll
        for (int i = 1; i < 8; i++) t = fminf(t, warp_red[i]);
        s_thrx = t;
    }
    __syncthreads();
    const float thrx = s_thrx;

    float ss = 0.f;
    for (int i = tid; i < OUT_DIM; i += 256) {
        float v = vals[i];
        bool keep = inwin[i] ? (v >= thrx) : (v > thr);
        float e = keep ? fmaxf(v, 0.f) : 0.f;
        ss = fmaf(e, e, ss);
    }
#pragma unroll
    for (int o = 16; o; o >>= 1) ss += __shfl_xor_sync(0xFFFFFFFFu, ss, o);
    if (lane == 0) warp_red[wid] = ss;
    __syncthreads();
    if (tid == 0) {
        float t = 0.f;
#pragma unroll
        for (int i = 0; i < 8; i++) t += warp_red[i];
        s_inv = 1.f / fmaxf(sqrtf(t), 1e-12f);
    }
    __syncthreads();
    const float inv = s_inv;

    float4* dst = (float4*)(out + rowoff);
    for (int g = tid; g < OUT_DIM / 4; g += 256) {
        const int i = g * 4;
        float4 o;
        { float v = vals[i];     o.x = ((inwin[i]     ? (v >= thrx) : (v > thr)) ? fmaxf(v, 0.f) : 0.f) * inv; }
        { float v = vals[i + 1]; o.y = ((inwin[i + 1] ? (v >= thrx) : (v > thr)) ? fmaxf(v, 0.f) : 0.f) * inv; }
        { float v = vals[i + 2]; o.z = ((inwin[i + 2] ? (v >= thrx) : (v > thr)) ? fmaxf(v, 0.f) : 0.f) * inv; }
        { float v = vals[i + 3]; o.w = ((inwin[i + 3] ? (v >= thrx) : (v > thr)) ? fmaxf(v, 0.f) : 0.f) * inv; }
        dst[g] = o;
    }
}

// ---------------------------------------------------------------------------
extern "C" void kernel_launch(void* const* d_in, const int* in_sizes, int n_in,
                              void* d_out, int out_size)
{
    const float* x = (const float*)d_in[0];
    const float* w = (const float*)d_in[1];
    float* out = (float*)d_out;
    (void)in_sizes; (void)n_in; (void)out_size;

    cudaFuncSetAttribute(gemm_mma_kernel,
                         cudaFuncAttributeMaxDynamicSharedMemorySize, SMEM_TOTAL);

    init_flag_kernel<<<1, 1>>>();
    scan_neg_kernel<<<2048, 256>>>((const float4*)x, BATCH * IN_DIM / 4);
    convert_w_kernel<<<4096, 256>>>((const float2*)w);
    convert_x_kernel<<<16384, 256>>>((const float2*)x);

    dim3 ggrid(OUT_DIM / BN, BATCH / BM);     // 32 x 128 CTAs
    gemm_mma_kernel<<<ggrid, 256, SMEM_TOTAL>>>(out);

    topk_fix_kernel<<<BATCH, 256>>>(out, x, w);
}